// round 8
// baseline (speedup 1.0000x reference)
#include <cuda_runtime.h>
#include <math.h>

#define N       1024
#define NN4     (N * N / 4)
#define RESTART 16
#define NV      17
#define K2C     0.3f
#define ACOEF   (4.0f + K2C)
#define EPSF    1e-12f
#define TPB     256
#define NBLK    512              /* 512 blocks x 256 threads x 2 points = NN4 */
#define NCYC    4
#define NPART   18

// ---------------- device scratch (allocations forbidden) --------------------
__device__ float4 g_P[NV][NN4];   // unnormalized basis; P[16] never materialized
__device__ float4 g_zA[NN4];      // z' ping-pong
__device__ float4 g_zB[NN4];
__device__ float4 g_x[NN4];
__device__ float  g_part[NPART][NBLK];
__device__ float  g_sig[NV];          // sigma_k = 1/(||P[k]||+eps)
__device__ float  g_hp[NV];           // previous step raw dots <P[k], z'>
__device__ float  g_e[NV];            // combo coeffs for next P
__device__ float  g_ew;               // combo coeff on z'
__device__ float  g_Q[NV * NV];       // <P[k], P[m]>
__device__ float  g_Hm[NV * RESTART]; // zeros below subdiag persist
__device__ float  g_y[RESTART];       // y_k * sigma_k (pre-scaled)
__device__ float  g_beta;
__device__ unsigned g_cnt;            // last-block counter (reset by last block)
__device__ volatile unsigned g_gen;   // grid-barrier generation
__device__ unsigned g_arrive;         // grid-barrier arrival counter

// ---------------- grid barrier ------------------------------------------------
__device__ __forceinline__ void gridBarrier() {
    __syncthreads();
    if (threadIdx.x == 0) {
        __threadfence();
        unsigned gen = g_gen;
        if (atomicAdd(&g_arrive, 1u) == (unsigned)(NBLK - 1)) {
            g_arrive = 0u;
            __threadfence();
            g_gen = gen + 1u;
        } else {
            while (g_gen == gen) __nanosleep(64);
        }
        __threadfence();
    }
    __syncthreads();
}

// ---------------- helpers ----------------------------------------------------
// per-thread geometry: two vertically adjacent points (rows 2q, 2q+1), col c
struct Geo {
    int i1, i2;      // f4 indices of the two centers
    int up, dn;      // f4 indices of row 2q-1, row 2q+2 (periodic)
    int l1, r1;      // scalar indices for row 2q wrap L/R
    int l2, r2;      // scalar indices for row 2q+1 wrap L/R
};

__device__ __forceinline__ Geo mkgeo() {
    int q   = blockIdx.x;        // row pair (TPB==256 => block = one row pair)
    int col = threadIdx.x;       // f4 column
    int r1  = q << 1, r2 = r1 + 1;
    Geo o;
    o.i1 = (r1 << 8) | col;
    o.i2 = (r2 << 8) | col;
    o.up = (((r1 - 1) & (N - 1)) << 8) | col;
    o.dn = (((r2 + 1) & (N - 1)) << 8) | col;
    int cl = ((col << 2) - 1) & (N - 1);
    int cr = ((col << 2) + 4) & (N - 1);
    o.l1 = (r1 << 10) | cl;  o.r1 = (r1 << 10) | cr;
    o.l2 = (r2 << 10) | cl;  o.r2 = (r2 << 10) | cr;
    return o;
}

// footprint for both points: 4 LDG.128 (C1,C2,U,D); L/R via warp shuffle,
// edge lanes (0/31) patch from memory.
__device__ __forceinline__ void loadF2(const float4* __restrict__ u4, const Geo& o,
                                       int lane,
                                       float4& C1, float4& NS1,
                                       float4& C2, float4& NS2) {
    C1 = u4[o.i1];
    C2 = u4[o.i2];
    float4 U = u4[o.up], D = u4[o.dn];
    float L1 = __shfl_up_sync(0xffffffffu, C1.w, 1);
    float R1 = __shfl_down_sync(0xffffffffu, C1.x, 1);
    float L2 = __shfl_up_sync(0xffffffffu, C2.w, 1);
    float R2 = __shfl_down_sync(0xffffffffu, C2.x, 1);
    if (lane == 0)  { L1 = ((const float*)u4)[o.l1]; L2 = ((const float*)u4)[o.l2]; }
    if (lane == 31) { R1 = ((const float*)u4)[o.r1]; R2 = ((const float*)u4)[o.r2]; }
    NS1.x = L1   + C1.y + U.x  + C2.x;
    NS1.y = C1.x + C1.z + U.y  + C2.y;
    NS1.z = C1.y + C1.w + U.z  + C2.z;
    NS1.w = C1.z + R1   + U.w  + C2.w;
    NS2.x = L2   + C2.y + C1.x + D.x;
    NS2.y = C2.x + C2.z + C1.y + D.y;
    NS2.z = C2.y + C2.w + C1.z + D.z;
    NS2.w = C2.z + R2   + C1.w + D.w;
}

__device__ __forceinline__ float dot4(float4 a, float4 b) {
    return a.x * b.x + a.y * b.y + a.z * b.z + a.w * b.w;
}

__device__ __forceinline__ float warpSum(float v) {
#pragma unroll
    for (int o = 16; o > 0; o >>= 1) v += __shfl_down_sync(0xffffffffu, v, o);
    return v;
}

__device__ __forceinline__ bool isLastBlock() {
    __shared__ unsigned s_last;
    if (threadIdx.x == 0)
        s_last = (atomicAdd(&g_cnt, 1u) == (unsigned)(NBLK - 1));
    __syncthreads();
    return s_last != 0;
}

// ---------------- phases (device functions) -----------------------------------
__device__ __forceinline__ void residPhase(const float4* __restrict__ b,
                                           const Geo& o, int lane) {
    float4 C1, NS1, C2, NS2;
    loadF2(g_x, o, lane, C1, NS1, C2, NS2);
    float4 b1 = b[o.i1], b2 = b[o.i2], r;
    r.x = b1.x - (ACOEF * C1.x - NS1.x);
    r.y = b1.y - (ACOEF * C1.y - NS1.y);
    r.z = b1.z - (ACOEF * C1.z - NS1.z);
    r.w = b1.w - (ACOEF * C1.w - NS1.w);
    g_P[0][o.i1] = r;
    r.x = b2.x - (ACOEF * C2.x - NS2.x);
    r.y = b2.y - (ACOEF * C2.y - NS2.y);
    r.z = b2.z - (ACOEF * C2.z - NS2.z);
    r.w = b2.w - (ACOEF * C2.w - NS2.w);
    g_P[0][o.i2] = r;
}

// One Arnoldi step (runtime j), single sweep, 2 points/thread.
__device__ __forceinline__ void arnPhase(int j, const Geo& o, int lane, int warp) {
    const float4* __restrict__ zin;
    float4* __restrict__ zout;
    if (j == 0)      { zin = g_P[0]; zout = g_zA; }
    else if (j & 1)  { zin = g_zA;   zout = g_zB; }
    else             { zin = g_zB;   zout = g_zA; }

    __shared__ float es[RESTART];
    if (threadIdx.x < RESTART) es[threadIdx.x] = g_e[threadIdx.x];
    __syncthreads();
    float ew = (j == 0) ? 1.0f : g_ew;

    // ---- pass 1: linear combination with 5-point footprints ----
    float4 pc1, pn1, pc2, pn2;
    {
        float4 C1, NS1, C2, NS2;
        loadF2(zin, o, lane, C1, NS1, C2, NS2);
        pc1.x = ew * C1.x;  pc1.y = ew * C1.y;  pc1.z = ew * C1.z;  pc1.w = ew * C1.w;
        pn1.x = ew * NS1.x; pn1.y = ew * NS1.y; pn1.z = ew * NS1.z; pn1.w = ew * NS1.w;
        pc2.x = ew * C2.x;  pc2.y = ew * C2.y;  pc2.z = ew * C2.z;  pc2.w = ew * C2.w;
        pn2.x = ew * NS2.x; pn2.y = ew * NS2.y; pn2.z = ew * NS2.z; pn2.w = ew * NS2.w;
    }
#pragma unroll 2
    for (int k = 0; k < j; k++) {
        float e = es[k];
        float4 C1, NS1, C2, NS2;
        loadF2(g_P[k], o, lane, C1, NS1, C2, NS2);
        pc1.x -= e * C1.x;  pc1.y -= e * C1.y;  pc1.z -= e * C1.z;  pc1.w -= e * C1.w;
        pn1.x -= e * NS1.x; pn1.y -= e * NS1.y; pn1.z -= e * NS1.z; pn1.w -= e * NS1.w;
        pc2.x -= e * C2.x;  pc2.y -= e * C2.y;  pc2.z -= e * C2.z;  pc2.w -= e * C2.w;
        pn2.x -= e * NS2.x; pn2.y -= e * NS2.y; pn2.z -= e * NS2.z; pn2.w -= e * NS2.w;
    }

    if (j > 0) { g_P[j][o.i1] = pc1; g_P[j][o.i2] = pc2; }

    float4 z1, z2;
    z1.x = ACOEF * pc1.x - pn1.x;
    z1.y = ACOEF * pc1.y - pn1.y;
    z1.z = ACOEF * pc1.z - pn1.z;
    z1.w = ACOEF * pc1.w - pn1.w;
    z2.x = ACOEF * pc2.x - pn2.x;
    z2.y = ACOEF * pc2.y - pn2.y;
    z2.z = ACOEF * pc2.z - pn2.z;
    z2.w = ACOEF * pc2.w - pn2.w;
    zout[o.i1] = z1;
    zout[o.i2] = z2;

    // ---- pass 2: dots (descending k: recent footprints are L1-warm) ----
    __shared__ float sred[NPART][TPB / 32];
#pragma unroll 4
    for (int k = j - 1; k >= 0; k--) {
        float d = warpSum(dot4(g_P[k][o.i1], z1) + dot4(g_P[k][o.i2], z2));
        if (lane == 0) sred[k][warp] = d;
    }
    {
        float dj = warpSum(dot4(pc1, z1) + dot4(pc2, z2));
        if (lane == 0) sred[j][warp] = dj;
        float nr = warpSum(dot4(pc1, pc1) + dot4(pc2, pc2));
        if (lane == 0) sred[j + 1][warp] = nr;
    }
    __syncthreads();
    int t = threadIdx.x;
    int nk = j + 2;
    if (t < nk) {
        float s = 0.f;
#pragma unroll
        for (int w = 0; w < TPB / 32; w++) s += sred[t][w];
        g_part[t][blockIdx.x] = s;
        __threadfence();
    }
    __syncthreads();

    if (isLastBlock()) {
        __shared__ float tot[NPART];
        for (int k = warp; k < nk; k += TPB / 32) {
            float s = 0.f;
            for (int b2 = lane; b2 < NBLK; b2 += 32) s += g_part[k][b2];
            s = warpSum(s);
            if (lane == 0) tot[k] = s;
        }
        __syncthreads();

        __shared__ float s_sig[NV], s_h[NV];
        if (t == 0) {
            float hn = sqrtf(tot[j + 1]);
            g_sig[j] = 1.0f / (hn + EPSF);
            if (j > 0) g_Hm[j * RESTART + (j - 1)] = hn;
            else       g_beta = hn;
            g_Q[j * NV + j] = tot[j + 1];
        }
        __syncthreads();
        if (t <= j) s_sig[t] = g_sig[t];
        __syncthreads();
        // Q column j via recurrence: <P[t],P[j]> = ew*hp[t] - sum_m e_m Q[t][m]
        if (t < j) {
            float q = ew * g_hp[t];
            for (int m = 0; m < j; m++) q -= es[m] * g_Q[t * NV + m];
            g_Q[t * NV + j] = q;
            g_Q[j * NV + t] = q;
        }
        if (t <= j) {
            s_h[t]  = s_sig[t] * s_sig[j] * tot[t];   // true h_k
            g_hp[t] = tot[t];
        }
        __syncthreads();
        if (t <= j) {
            float gh = 0.f;
            for (int m = 0; m <= j; m++)
                gh += s_sig[t] * s_sig[m] * g_Q[t * NV + m] * s_h[m];
            float c = 2.0f * s_h[t] - gh;             // h + h2,  h2 = h - Gh
            g_Hm[t * RESTART + j] = c;
            g_e[t] = c * s_sig[t];
        }
        if (t == 0) { g_ew = s_sig[j]; g_cnt = 0; }
    }
}

// ||P[16]||^2 -> Hm[16][15]; then 16x16 normal-equations solve; y pre-scaled
__device__ __forceinline__ void finPhase(const Geo& o, int lane, int warp) {
    __shared__ float es2[RESTART];
    if (threadIdx.x < RESTART) es2[threadIdx.x] = g_e[threadIdx.x];
    __syncthreads();
    float ew = g_ew;

    float4 za = g_zB[o.i1], zb = g_zB[o.i2];   // z' of step 15 (odd -> zB)
    float4 p1, p2;
    p1.x = ew * za.x; p1.y = ew * za.y; p1.z = ew * za.z; p1.w = ew * za.w;
    p2.x = ew * zb.x; p2.y = ew * zb.y; p2.z = ew * zb.z; p2.w = ew * zb.w;
#pragma unroll 4
    for (int k = 0; k < RESTART; k++) {
        float e = es2[k];
        float4 v = g_P[k][o.i1];
        p1.x -= e * v.x; p1.y -= e * v.y; p1.z -= e * v.z; p1.w -= e * v.w;
        v = g_P[k][o.i2];
        p2.x -= e * v.x; p2.y -= e * v.y; p2.z -= e * v.z; p2.w -= e * v.w;
    }
    __shared__ float sred2[TPB / 32];
    float nr = warpSum(dot4(p1, p1) + dot4(p2, p2));
    if (lane == 0) sred2[warp] = nr;
    __syncthreads();
    if (threadIdx.x == 0) {
        float s = 0.f;
#pragma unroll
        for (int w = 0; w < TPB / 32; w++) s += sred2[w];
        g_part[0][blockIdx.x] = s;
        __threadfence();
    }
    __syncthreads();

    if (isLastBlock()) {
        int t = threadIdx.x;
        __shared__ float tot0;
        if (warp == 0) {
            float s = 0.f;
            for (int b2 = lane; b2 < NBLK; b2 += 32) s += g_part[0][b2];
            s = warpSum(s);
            if (lane == 0) tot0 = s;
        }
        __syncthreads();
        if (t == 0) g_Hm[16 * RESTART + 15] = sqrtf(tot0);
        __syncthreads();

        __shared__ float sG[RESTART][RESTART], sf[RESTART], rhs[RESTART];
        {
            int a = t >> 4, b2 = t & 15;     // 256 threads = 16x16
            float su = 0.f;
            for (int r = 0; r < NV; r++)
                su += g_Hm[r * RESTART + a] * g_Hm[r * RESTART + b2];
            sG[a][b2] = su + ((a == b2) ? EPSF : 0.f);
        }
        if (t < RESTART) rhs[t] = g_Hm[t] * g_beta;   // Hm row 0
        __syncthreads();

        for (int p = 0; p < RESTART; p++) {
            if (t > p && t < RESTART) sf[t] = sG[t][p] / sG[p][p];
            __syncthreads();
            int r = t >> 4, c = t & 15;
            if (r > p && c > p) sG[r][c] -= sf[r] * sG[p][c];
            if (t > p && t < RESTART) rhs[t] -= sf[t] * rhs[p];
            __syncthreads();
        }
        if (t == 0) {
            for (int p = RESTART - 1; p >= 0; p--) {
                float su = rhs[p];
                for (int c = p + 1; c < RESTART; c++) su -= sG[p][c] * rhs[c];
                rhs[p] = su / sG[p][p];
            }
        }
        __syncthreads();
        if (t < RESTART) g_y[t] = rhs[t] * g_sig[t];
        if (t == 0) g_cnt = 0;
    }
}

__device__ __forceinline__ void xupdPhase(const Geo& o, float4* __restrict__ out) {
    __shared__ float ys[RESTART];
    if (threadIdx.x < RESTART) ys[threadIdx.x] = g_y[threadIdx.x];
    __syncthreads();
    float4 s1 = g_x[o.i1], s2 = g_x[o.i2];
#pragma unroll 4
    for (int k = 0; k < RESTART; k++) {
        float y = ys[k];
        float4 v = g_P[k][o.i1];
        s1.x += y * v.x; s1.y += y * v.y; s1.z += y * v.z; s1.w += y * v.w;
        v = g_P[k][o.i2];
        s2.x += y * v.x; s2.y += y * v.y; s2.z += y * v.z; s2.w += y * v.w;
    }
    g_x[o.i1] = s1;
    g_x[o.i2] = s2;
    if (out) { out[o.i1] = s1; out[o.i2] = s2; }
}

// ---------------- the persistent mega-kernel ----------------------------------
__global__ void __launch_bounds__(TPB, 4) k_all(const float4* __restrict__ b,
                                                const float4* __restrict__ guess,
                                                float4* __restrict__ out) {
    Geo o = mkgeo();
    int lane = threadIdx.x & 31, warp = threadIdx.x >> 5;

    g_x[o.i1] = guess[o.i1];
    g_x[o.i2] = guess[o.i2];
    gridBarrier();

    for (int c = 0; c < NCYC; c++) {
        residPhase(b, o, lane);
        gridBarrier();

        for (int j = 0; j < RESTART; j++) {
            arnPhase(j, o, lane, warp);
            gridBarrier();
        }

        finPhase(o, lane, warp);
        gridBarrier();

        xupdPhase(o, (c == NCYC - 1) ? out : nullptr);
        if (c < NCYC - 1) gridBarrier();
    }
}

// ---------------- host orchestration ----------------------------------------
extern "C" void kernel_launch(void* const* d_in, const int* in_sizes, int n_in,
                              void* d_out, int out_size) {
    (void)in_sizes; (void)n_in; (void)out_size;
    const float4* src   = (const float4*)d_in[0];
    const float4* guess = (const float4*)d_in[1];
    float4* out = (float4*)d_out;

    k_all<<<NBLK, TPB>>>(src, guess, out);
}

// round 9
// speedup vs baseline: 1.3337x; 1.3337x over previous
#include <cuda_runtime.h>
#include <math.h>

#define N       1024
#define NN4     (N * N / 4)
#define RESTART 16
#define NSV     16               /* stored basis s_0..s_15 */
#define TPB     256
#define NBLK    512              /* 512 blocks x 256 threads x 2 points = NN4 */
#define NCYC    4

// ---------------- device scratch (allocations forbidden) --------------------
__device__ float4 g_S[NSV][NN4];  // Chebyshev basis s_0..s_15 (s_16 never stored)
__device__ float4 g_x[NN4];
__device__ float  g_part[3][NBLK];
__device__ float  g_mu[33];       // moments <r, T_k(Atil) r>, k=0..32
__device__ float  g_c[RESTART];   // solution coefficients in s-basis
__device__ unsigned g_cnt;

// ---------------- helpers ----------------------------------------------------
// per-thread geometry: two vertically adjacent points (rows 2q, 2q+1), col c
struct Geo {
    int i1, i2;      // f4 indices of the two centers
    int up, dn;      // f4 indices of row 2q-1, row 2q+2 (periodic)
    int l1, r1, l2, r2;  // scalar wrap indices
};

__device__ __forceinline__ Geo mkgeo() {
    int q   = blockIdx.x;
    int col = threadIdx.x;
    int r1  = q << 1, r2 = r1 + 1;
    Geo o;
    o.i1 = (r1 << 8) | col;
    o.i2 = (r2 << 8) | col;
    o.up = (((r1 - 1) & (N - 1)) << 8) | col;
    o.dn = (((r2 + 1) & (N - 1)) << 8) | col;
    int cl = ((col << 2) - 1) & (N - 1);
    int cr = ((col << 2) + 4) & (N - 1);
    o.l1 = (r1 << 10) | cl;  o.r1 = (r1 << 10) | cr;
    o.l2 = (r2 << 10) | cl;  o.r2 = (r2 << 10) | cr;
    return o;
}

// footprint: centers C1,C2 + neighbor-sums NS1,NS2 (4 LDG.128; L/R via shuffle)
__device__ __forceinline__ void loadF2(const float4* __restrict__ u4, const Geo& o,
                                       int lane,
                                       float4& C1, float4& NS1,
                                       float4& C2, float4& NS2) {
    C1 = u4[o.i1];
    C2 = u4[o.i2];
    float4 U = u4[o.up], D = u4[o.dn];
    float L1 = __shfl_up_sync(0xffffffffu, C1.w, 1);
    float R1 = __shfl_down_sync(0xffffffffu, C1.x, 1);
    float L2 = __shfl_up_sync(0xffffffffu, C2.w, 1);
    float R2 = __shfl_down_sync(0xffffffffu, C2.x, 1);
    if (lane == 0)  { L1 = ((const float*)u4)[o.l1]; L2 = ((const float*)u4)[o.l2]; }
    if (lane == 31) { R1 = ((const float*)u4)[o.r1]; R2 = ((const float*)u4)[o.r2]; }
    NS1.x = L1   + C1.y + U.x  + C2.x;
    NS1.y = C1.x + C1.z + U.y  + C2.y;
    NS1.z = C1.y + C1.w + U.z  + C2.z;
    NS1.w = C1.z + R1   + U.w  + C2.w;
    NS2.x = L2   + C2.y + C1.x + D.x;
    NS2.y = C2.x + C2.z + C1.y + D.y;
    NS2.z = C2.y + C2.w + C1.z + D.z;
    NS2.w = C2.z + R2   + C1.w + D.w;
}

__device__ __forceinline__ float dot4(float4 a, float4 b) {
    return a.x * b.x + a.y * b.y + a.z * b.z + a.w * b.w;
}

__device__ __forceinline__ float warpSum(float v) {
#pragma unroll
    for (int o = 16; o > 0; o >>= 1) v += __shfl_down_sync(0xffffffffu, v, o);
    return v;
}

__device__ __forceinline__ bool isLastBlock() {
    __shared__ unsigned s_last;
    if (threadIdx.x == 0)
        s_last = (atomicAdd(&g_cnt, 1u) == (unsigned)(NBLK - 1));
    __syncthreads();
    return s_last != 0;
}

// ---------------- kernels ------------------------------------------------------
__global__ void __launch_bounds__(TPB) k_init(const float4* __restrict__ guess) {
    Geo o = mkgeo();
    g_x[o.i1] = guess[o.i1];
    g_x[o.i2] = guess[o.i2];
}

// s_0 = r = b - A(x),  A(u) = 4.3u - NS(u)
__global__ void __launch_bounds__(TPB) k_resid(const float4* __restrict__ b) {
    Geo o = mkgeo();
    int lane = threadIdx.x & 31;
    float4 C1, NS1, C2, NS2;
    loadF2(g_x, o, lane, C1, NS1, C2, NS2);
    float4 b1 = b[o.i1], b2 = b[o.i2], r;
    r.x = b1.x - (4.3f * C1.x - NS1.x);
    r.y = b1.y - (4.3f * C1.y - NS1.y);
    r.z = b1.z - (4.3f * C1.z - NS1.z);
    r.w = b1.w - (4.3f * C1.w - NS1.w);
    g_S[0][o.i1] = r;
    r.x = b2.x - (4.3f * C2.x - NS2.x);
    r.y = b2.y - (4.3f * C2.y - NS2.y);
    r.z = b2.z - (4.3f * C2.z - NS2.z);
    r.w = b2.w - (4.3f * C2.w - NS2.w);
    g_S[0][o.i2] = r;
}

// Chebyshev sweep i (i = 0..15):
//   Atil(u) = -NS(u)/4  (spectrum [-1,1] since A in [0.3, 8.3], d=4.3, e=4)
//   i==0 : s_1 = Atil s_0 = -NS/4
//   i>=1 : s_{i+1} = 2 Atil s_i - s_{i-1} = -NS/2 - s_{i-1}
//   store s_{i+1} only for i<15 (s_16 exists just for its moments)
//   dots: a = <s_i,s_i>, b = <s_i,s_{i+1}>, (i==15 also) a2 = <s_16,s_16>
//   last block: mu[2i] = 2a - mu0, mu[2i+1] = 2b - mu1 (mu0=a_0, mu1=b_0),
//               mu[32] = 2*a2 - mu0
__global__ void __launch_bounds__(TPB) k_sweep(int i) {
    Geo o = mkgeo();
    int lane = threadIdx.x & 31, warp = threadIdx.x >> 5;

    float4 C1, NS1, C2, NS2;
    loadF2(g_S[i], o, lane, C1, NS1, C2, NS2);

    float4 n1, n2;
    if (i == 0) {
        n1.x = -0.25f * NS1.x; n1.y = -0.25f * NS1.y;
        n1.z = -0.25f * NS1.z; n1.w = -0.25f * NS1.w;
        n2.x = -0.25f * NS2.x; n2.y = -0.25f * NS2.y;
        n2.z = -0.25f * NS2.z; n2.w = -0.25f * NS2.w;
    } else {
        float4 p1 = g_S[i - 1][o.i1], p2 = g_S[i - 1][o.i2];
        n1.x = -0.5f * NS1.x - p1.x; n1.y = -0.5f * NS1.y - p1.y;
        n1.z = -0.5f * NS1.z - p1.z; n1.w = -0.5f * NS1.w - p1.w;
        n2.x = -0.5f * NS2.x - p2.x; n2.y = -0.5f * NS2.y - p2.y;
        n2.z = -0.5f * NS2.z - p2.z; n2.w = -0.5f * NS2.w - p2.w;
    }
    if (i < 15) { g_S[i + 1][o.i1] = n1; g_S[i + 1][o.i2] = n2; }

    float a  = dot4(C1, C1) + dot4(C2, C2);
    float bb = dot4(C1, n1) + dot4(C2, n2);
    float a2 = (i == 15) ? (dot4(n1, n1) + dot4(n2, n2)) : 0.f;

    __shared__ float sred[3][TPB / 32];
    float v0 = warpSum(a), v1 = warpSum(bb), v2 = warpSum(a2);
    if (lane == 0) { sred[0][warp] = v0; sred[1][warp] = v1; sred[2][warp] = v2; }
    __syncthreads();
    int t = threadIdx.x;
    if (t < 3) {
        float s = 0.f;
#pragma unroll
        for (int w = 0; w < TPB / 32; w++) s += sred[t][w];
        g_part[t][blockIdx.x] = s;
        __threadfence();
    }
    __syncthreads();

    if (isLastBlock()) {
        __shared__ float tot[3];
        if (warp < 3) {
            float s = 0.f;
            for (int b2 = lane; b2 < NBLK; b2 += 32) s += g_part[warp][b2];
            s = warpSum(s);
            if (lane == 0) tot[warp] = s;
        }
        __syncthreads();
        if (t == 0) {
            if (i == 0) {
                g_mu[0] = tot[0];
                g_mu[1] = tot[1];
            } else {
                float mu0 = g_mu[0], mu1 = g_mu[1];
                g_mu[2 * i]     = 2.f * tot[0] - mu0;
                g_mu[2 * i + 1] = 2.f * tot[1] - mu1;
                if (i == 15) g_mu[32] = 2.f * tot[2] - mu0;
            }
            g_cnt = 0;
        }
    }
}

// Scalar solve (1 block, fp64):
//   M[a][b] = 0.5*(mu[a+b] + mu[|a-b|])           (17x17 Gram of s_0..s_16)
//   T: A s_0 = 4.3 s_0 + 4 s_1 ; A s_j = 4.3 s_j + 2 s_{j+1} + 2 s_{j-1}
//   G = T' M T (16x16), rhs = T' M e0 ; solve (G + ridge I) c = rhs
__global__ void k_fin() {
    int t = threadIdx.x;
    __shared__ double mu[33];
    if (t < 33) mu[t] = (double)g_mu[t];
    __syncthreads();

    __shared__ double M[17][17];
    for (int idx = t; idx < 289; idx += TPB) {
        int a = idx / 17, b = idx % 17;
        int d = a - b; if (d < 0) d = -d;
        M[a][b] = 0.5 * (mu[a + b] + mu[d]);
    }
    __syncthreads();

    __shared__ double W[17][16];                      // W = M*T
    for (int idx = t; idx < 272; idx += TPB) {
        int r = idx / 16, b = idx % 16;
        double w = 4.3 * M[r][b];
        w += (b == 0) ? 4.0 * M[r][1] : 2.0 * (M[r][b + 1] + M[r][b - 1]);
        W[r][b] = w;
    }
    __syncthreads();

    __shared__ double G[16][16], rhs[16], sf[16];
    {
        int a = t >> 4, b = t & 15;                   // 256 threads = 16x16
        double g = 4.3 * W[a][b];
        g += (a == 0) ? 4.0 * W[1][b] : 2.0 * (W[a + 1][b] + W[a - 1][b]);
        G[a][b] = g;
    }
    if (t < 16) {
        double r = 4.3 * M[t][0];
        r += (t == 0) ? 4.0 * M[1][0] : 2.0 * (M[t + 1][0] + M[t - 1][0]);
        rhs[t] = r;
    }
    __syncthreads();
    if (t == 0) {
        double tr = 0.0;
        for (int k2 = 0; k2 < 16; k2++) tr += G[k2][k2];
        double ridge = 1e-12 + 1e-10 * (tr / 16.0);
        for (int k2 = 0; k2 < 16; k2++) G[k2][k2] += ridge;
    }
    __syncthreads();

    for (int p = 0; p < 16; p++) {
        if (t > p && t < 16) sf[t] = G[t][p] / G[p][p];
        __syncthreads();
        int r = t >> 4, c = t & 15;
        if (r > p && c > p) G[r][c] -= sf[r] * G[p][c];
        if (t > p && t < 16) rhs[t] -= sf[t] * rhs[p];
        __syncthreads();
    }
    if (t == 0) {
        for (int p = 15; p >= 0; p--) {
            double su = rhs[p];
            for (int c = p + 1; c < 16; c++) su -= G[p][c] * rhs[c];
            rhs[p] = su / G[p][p];
        }
    }
    __syncthreads();
    if (t < 16) g_c[t] = (float)rhs[t];
}

// x += sum_k c_k s_k ; optionally emit
__global__ void __launch_bounds__(TPB) k_xupd(float4* __restrict__ out) {
    __shared__ float cs[RESTART];
    if (threadIdx.x < RESTART) cs[threadIdx.x] = g_c[threadIdx.x];
    __syncthreads();
    Geo o = mkgeo();
    float4 s1 = g_x[o.i1], s2 = g_x[o.i2];
#pragma unroll 4
    for (int k = 0; k < RESTART; k++) {
        float y = cs[k];
        float4 v = g_S[k][o.i1];
        s1.x += y * v.x; s1.y += y * v.y; s1.z += y * v.z; s1.w += y * v.w;
        v = g_S[k][o.i2];
        s2.x += y * v.x; s2.y += y * v.y; s2.z += y * v.z; s2.w += y * v.w;
    }
    g_x[o.i1] = s1;
    g_x[o.i2] = s2;
    if (out) { out[o.i1] = s1; out[o.i2] = s2; }
}

// ---------------- host orchestration ----------------------------------------
extern "C" void kernel_launch(void* const* d_in, const int* in_sizes, int n_in,
                              void* d_out, int out_size) {
    (void)in_sizes; (void)n_in; (void)out_size;
    const float4* src   = (const float4*)d_in[0];
    const float4* guess = (const float4*)d_in[1];
    float4* out = (float4*)d_out;

    k_init<<<NBLK, TPB>>>(guess);

    for (int c = 0; c < NCYC; c++) {
        k_resid<<<NBLK, TPB>>>(src);
        for (int i = 0; i < RESTART; i++)
            k_sweep<<<NBLK, TPB>>>(i);
        k_fin<<<1, TPB>>>();
        k_xupd<<<NBLK, TPB>>>(c == NCYC - 1 ? out : nullptr);
    }
}

// round 10
// speedup vs baseline: 2.1041x; 1.5777x over previous
#include <cuda_runtime.h>
#include <math.h>

#define N       1024
#define NN4     (N * N / 4)
#define RESTART 16
#define TPB     256
#define NBLK    512              /* 512 blocks x 256 threads x 2 points = NN4 */
#define NCYC    4

// ---------------- device scratch (allocations forbidden) --------------------
__device__ float4 g_S[16][NN4];   // Chebyshev basis s_0..s_15
__device__ float4 g_x[NN4];
__device__ float  g_part[3][NBLK];
__device__ float  g_mu[33];       // moments <r, T_k(Atil) r>
__device__ float  g_c[RESTART];
__device__ unsigned g_cnt;
__device__ volatile unsigned g_gen;
__device__ unsigned g_arrive;

// ---------------- grid barrier ------------------------------------------------
__device__ __forceinline__ void gridBarrier() {
    __syncthreads();
    if (threadIdx.x == 0) {
        __threadfence();
        unsigned gen = g_gen;
        if (atomicAdd(&g_arrive, 1u) == (unsigned)(NBLK - 1)) {
            g_arrive = 0u;
            __threadfence();
            g_gen = gen + 1u;
        } else {
            while (g_gen == gen) __nanosleep(64);
        }
        __threadfence();
    }
    __syncthreads();
}

// ---------------- helpers ----------------------------------------------------
struct Geo {
    int i1, i2;      // f4 indices of the two centers (rows 2q, 2q+1)
    int up, dn;      // f4 indices of rows 2q-1, 2q+2 (periodic)
    int l1, r1, l2, r2;  // scalar wrap indices
};

__device__ __forceinline__ Geo mkgeo() {
    int q   = blockIdx.x;
    int col = threadIdx.x;
    int r1  = q << 1, r2 = r1 + 1;
    Geo o;
    o.i1 = (r1 << 8) | col;
    o.i2 = (r2 << 8) | col;
    o.up = (((r1 - 1) & (N - 1)) << 8) | col;
    o.dn = (((r2 + 1) & (N - 1)) << 8) | col;
    int cl = ((col << 2) - 1) & (N - 1);
    int cr = ((col << 2) + 4) & (N - 1);
    o.l1 = (r1 << 10) | cl;  o.r1 = (r1 << 10) | cr;
    o.l2 = (r2 << 10) | cl;  o.r2 = (r2 << 10) | cr;
    return o;
}

// neighbor-sums for registers-resident centers C1,C2: only U/D rows + edge
// scalars come from memory (u4 = the vector s_i as stored in g_S)
__device__ __forceinline__ void nsFromRegs(const float4* __restrict__ u4, const Geo& o,
                                           int lane,
                                           const float4& C1, const float4& C2,
                                           float4& NS1, float4& NS2) {
    float4 U = u4[o.up], D = u4[o.dn];
    float L1 = __shfl_up_sync(0xffffffffu, C1.w, 1);
    float R1 = __shfl_down_sync(0xffffffffu, C1.x, 1);
    float L2 = __shfl_up_sync(0xffffffffu, C2.w, 1);
    float R2 = __shfl_down_sync(0xffffffffu, C2.x, 1);
    if (lane == 0)  { L1 = ((const float*)u4)[o.l1]; L2 = ((const float*)u4)[o.l2]; }
    if (lane == 31) { R1 = ((const float*)u4)[o.r1]; R2 = ((const float*)u4)[o.r2]; }
    NS1.x = L1   + C1.y + U.x  + C2.x;
    NS1.y = C1.x + C1.z + U.y  + C2.y;
    NS1.z = C1.y + C1.w + U.z  + C2.z;
    NS1.w = C1.z + R1   + U.w  + C2.w;
    NS2.x = L2   + C2.y + C1.x + D.x;
    NS2.y = C2.x + C2.z + C1.y + D.y;
    NS2.z = C2.y + C2.w + C1.z + D.z;
    NS2.w = C2.z + R2   + C1.w + D.w;
}

// full footprint load (for resid, which reads x from memory)
__device__ __forceinline__ void loadF2(const float4* __restrict__ u4, const Geo& o,
                                       int lane,
                                       float4& C1, float4& NS1,
                                       float4& C2, float4& NS2) {
    C1 = u4[o.i1];
    C2 = u4[o.i2];
    nsFromRegs(u4, o, lane, C1, C2, NS1, NS2);
}

__device__ __forceinline__ float dot4(float4 a, float4 b) {
    return a.x * b.x + a.y * b.y + a.z * b.z + a.w * b.w;
}

__device__ __forceinline__ float warpSum(float v) {
#pragma unroll
    for (int o = 16; o > 0; o >>= 1) v += __shfl_down_sync(0xffffffffu, v, o);
    return v;
}

__device__ __forceinline__ bool isLastBlock() {
    __shared__ unsigned s_last;
    if (threadIdx.x == 0)
        s_last = (atomicAdd(&g_cnt, 1u) == (unsigned)(NBLK - 1));
    __syncthreads();
    return s_last != 0;
}

// ---------------- fp64 scalar solve (block 0 only) -----------------------------
__device__ void finSolve() {
    int t = threadIdx.x;
    __shared__ double mu[33];
    if (t < 33) mu[t] = (double)g_mu[t];
    __syncthreads();

    __shared__ double M[17][17];
    for (int idx = t; idx < 289; idx += TPB) {
        int a = idx / 17, b = idx % 17;
        int d = a - b; if (d < 0) d = -d;
        M[a][b] = 0.5 * (mu[a + b] + mu[d]);
    }
    __syncthreads();

    __shared__ double W[17][16];                      // W = M*T
    for (int idx = t; idx < 272; idx += TPB) {
        int r = idx / 16, b = idx % 16;
        double w = 4.3 * M[r][b];
        w += (b == 0) ? 4.0 * M[r][1] : 2.0 * (M[r][b + 1] + M[r][b - 1]);
        W[r][b] = w;
    }
    __syncthreads();

    __shared__ double G[16][16], rhs[16], sf[16];
    {
        int a = t >> 4, b = t & 15;                   // 256 threads = 16x16
        double g = 4.3 * W[a][b];
        g += (a == 0) ? 4.0 * W[1][b] : 2.0 * (W[a + 1][b] + W[a - 1][b]);
        G[a][b] = g;
    }
    if (t < 16) {
        double r = 4.3 * M[t][0];
        r += (t == 0) ? 4.0 * M[1][0] : 2.0 * (M[t + 1][0] + M[t - 1][0]);
        rhs[t] = r;
    }
    __syncthreads();
    if (t == 0) {
        double tr = 0.0;
        for (int k = 0; k < 16; k++) tr += G[k][k];
        double ridge = 1e-12 + 1e-10 * (tr / 16.0);
        for (int k = 0; k < 16; k++) G[k][k] += ridge;
    }
    __syncthreads();

    for (int p = 0; p < 16; p++) {
        if (t > p && t < 16) sf[t] = G[t][p] / G[p][p];
        __syncthreads();
        int r = t >> 4, c = t & 15;
        if (r > p && c > p) G[r][c] -= sf[r] * G[p][c];
        if (t > p && t < 16) rhs[t] -= sf[t] * rhs[p];
        __syncthreads();
    }
    if (t == 0) {
        for (int p = 15; p >= 0; p--) {
            double su = rhs[p];
            for (int c = p + 1; c < 16; c++) su -= G[p][c] * rhs[c];
            rhs[p] = su / G[p][p];
        }
    }
    __syncthreads();
    if (t < 16) g_c[t] = (float)rhs[t];
}

// ---------------- the persistent kernel ----------------------------------------
__global__ void __launch_bounds__(TPB, 4) k_all(const float4* __restrict__ b,
                                                const float4* __restrict__ guess,
                                                float4* __restrict__ out) {
    Geo o = mkgeo();
    int lane = threadIdx.x & 31, warp = threadIdx.x >> 5;

    g_x[o.i1] = guess[o.i1];
    g_x[o.i2] = guess[o.i2];
    gridBarrier();

    for (int c = 0; c < NCYC; c++) {
        // ---- residual: s_0 = b - A(x),  A(u) = 4.3u - NS(u) ----
        float4 s1, s2;       // register-resident s_i (current)
        float4 p1, p2;       // register-resident s_{i-1}
        {
            float4 C1, NS1, C2, NS2;
            loadF2(g_x, o, lane, C1, NS1, C2, NS2);
            float4 b1 = b[o.i1], b2 = b[o.i2];
            s1.x = b1.x - (4.3f * C1.x - NS1.x);
            s1.y = b1.y - (4.3f * C1.y - NS1.y);
            s1.z = b1.z - (4.3f * C1.z - NS1.z);
            s1.w = b1.w - (4.3f * C1.w - NS1.w);
            s2.x = b2.x - (4.3f * C2.x - NS2.x);
            s2.y = b2.y - (4.3f * C2.y - NS2.y);
            s2.z = b2.z - (4.3f * C2.z - NS2.z);
            s2.w = b2.w - (4.3f * C2.w - NS2.w);
            g_S[0][o.i1] = s1;
            g_S[0][o.i2] = s2;
            p1 = s1; p2 = s2;   // dummy (unused at i=0)
        }
        gridBarrier();

        // ---- 16 Chebyshev sweeps, state in registers ----
        for (int i = 0; i < RESTART; i++) {
            float4 T1, T2;
            nsFromRegs(g_S[i], o, lane, s1, s2, T1, T2);   // only U/D + edges from mem

            float4 n1, n2;
            if (i == 0) {
                n1.x = -0.25f * T1.x; n1.y = -0.25f * T1.y;
                n1.z = -0.25f * T1.z; n1.w = -0.25f * T1.w;
                n2.x = -0.25f * T2.x; n2.y = -0.25f * T2.y;
                n2.z = -0.25f * T2.z; n2.w = -0.25f * T2.w;
            } else {
                n1.x = -0.5f * T1.x - p1.x; n1.y = -0.5f * T1.y - p1.y;
                n1.z = -0.5f * T1.z - p1.z; n1.w = -0.5f * T1.w - p1.w;
                n2.x = -0.5f * T2.x - p2.x; n2.y = -0.5f * T2.y - p2.y;
                n2.z = -0.5f * T2.z - p2.z; n2.w = -0.5f * T2.w - p2.w;
            }
            if (i < RESTART - 1) { g_S[i + 1][o.i1] = n1; g_S[i + 1][o.i2] = n2; }

            float a  = dot4(s1, s1) + dot4(s2, s2);
            float bb = dot4(s1, n1) + dot4(s2, n2);
            float a2 = (i == RESTART - 1) ? (dot4(n1, n1) + dot4(n2, n2)) : 0.f;

            __shared__ float sred[3][TPB / 32];
            float v0 = warpSum(a), v1 = warpSum(bb), v2 = warpSum(a2);
            if (lane == 0) { sred[0][warp] = v0; sred[1][warp] = v1; sred[2][warp] = v2; }
            __syncthreads();
            int t = threadIdx.x;
            if (t < 3) {
                float s = 0.f;
#pragma unroll
                for (int w = 0; w < TPB / 32; w++) s += sred[t][w];
                g_part[t][blockIdx.x] = s;
                __threadfence();
            }
            __syncthreads();

            if (isLastBlock()) {
                __shared__ float tot[3];
                if (warp < 3) {
                    float s = 0.f;
                    for (int b2 = lane; b2 < NBLK; b2 += 32) s += g_part[warp][b2];
                    s = warpSum(s);
                    if (lane == 0) tot[warp] = s;
                }
                __syncthreads();
                if (t == 0) {
                    if (i == 0) {
                        g_mu[0] = tot[0];
                        g_mu[1] = tot[1];
                    } else {
                        float mu0 = g_mu[0], mu1 = g_mu[1];
                        g_mu[2 * i]     = 2.f * tot[0] - mu0;
                        g_mu[2 * i + 1] = 2.f * tot[1] - mu1;
                        if (i == RESTART - 1) g_mu[32] = 2.f * tot[2] - mu0;
                    }
                    g_cnt = 0;
                }
            }
            p1 = s1; p2 = s2;
            s1 = n1; s2 = n2;
            gridBarrier();
        }
        // after loop: p = s_15 (registers), s = s_16 (discarded)

        // ---- scalar solve (block 0) ----
        if (blockIdx.x == 0) finSolve();
        gridBarrier();

        // ---- x += sum_k c_k s_k  (s_15 from registers) ----
        {
            __shared__ float cs[RESTART];
            if (threadIdx.x < RESTART) cs[threadIdx.x] = g_c[threadIdx.x];
            __syncthreads();
            float4 x1 = g_x[o.i1], x2 = g_x[o.i2];
#pragma unroll 4
            for (int k = 0; k < RESTART - 1; k++) {
                float y = cs[k];
                float4 v = g_S[k][o.i1];
                x1.x += y * v.x; x1.y += y * v.y; x1.z += y * v.z; x1.w += y * v.w;
                v = g_S[k][o.i2];
                x2.x += y * v.x; x2.y += y * v.y; x2.z += y * v.z; x2.w += y * v.w;
            }
            float y15 = cs[RESTART - 1];
            x1.x += y15 * p1.x; x1.y += y15 * p1.y; x1.z += y15 * p1.z; x1.w += y15 * p1.w;
            x2.x += y15 * p2.x; x2.y += y15 * p2.y; x2.z += y15 * p2.z; x2.w += y15 * p2.w;
            g_x[o.i1] = x1;
            g_x[o.i2] = x2;
            if (c == NCYC - 1) { out[o.i1] = x1; out[o.i2] = x2; }
            else gridBarrier();
        }
    }
}

// ---------------- host orchestration ----------------------------------------
extern "C" void kernel_launch(void* const* d_in, const int* in_sizes, int n_in,
                              void* d_out, int out_size) {
    (void)in_sizes; (void)n_in; (void)out_size;
    const float4* src   = (const float4*)d_in[0];
    const float4* guess = (const float4*)d_in[1];
    float4* out = (float4*)d_out;

    k_all<<<NBLK, TPB>>>(src, guess, out);
}